// round 1
// baseline (speedup 1.0000x reference)
#include <cuda_runtime.h>

#define B_DIM   128
#define INDIM   256
#define OUTDIM  256
#define N_COEF  11
#define N_KNOTS 15
#define ORDER   3

__global__ __launch_bounds__(128)
void kan_kernel(const float* __restrict__ x,
                const float* __restrict__ grid,
                const float* __restrict__ coef,
                const float* __restrict__ rw,
                const float* __restrict__ uw,
                float* __restrict__ out)
{
    const int b   = blockIdx.x;
    const int oh  = blockIdx.y;
    const int tid = threadIdx.x;

    __shared__ float  s_g[N_KNOTS];
    __shared__ float4 s_w[INDIM];     // 4 nonzero basis values per input
    __shared__ int    s_idx[INDIM];   // coef window start (0..7)
    __shared__ float  s_act[INDIM];   // silu(x)

    if (tid < N_KNOTS) s_g[tid] = grid[tid];   // grid is broadcast; first 15 floats are the knots
    __syncthreads();

    // Phase 1: per-(b,i) basis weights via local de Boor recurrence
    for (int i = tid; i < INDIM; i += 128) {
        float xv = x[b * INDIM + i];

        // interval index j such that g[j] <= x < g[j+1]
        int j = 0;
        #pragma unroll
        for (int t = 1; t <= N_KNOTS - 2; ++t) j += (xv >= s_g[t]) ? 1 : 0;
        j = max(min(j, 10), 3);   // x in [-1,1) always lands in [3,10]

        float lft[ORDER + 1], rgt[ORDER + 1];
        #pragma unroll
        for (int t = 1; t <= ORDER; ++t) {
            lft[t] = xv - s_g[j + 1 - t];
            rgt[t] = s_g[j + t] - xv;
        }
        float N[ORDER + 1];
        N[0] = 1.0f;
        #pragma unroll
        for (int p = 1; p <= ORDER; ++p) {
            float saved = 0.0f;
            #pragma unroll
            for (int r = 0; r < p; ++r) {
                float temp = N[r] / (rgt[r + 1] + lft[p - r]);
                N[r] = saved + rgt[r + 1] * temp;
                saved = lft[p - r] * temp;
            }
            N[p] = saved;
        }

        s_w[i]   = make_float4(N[0], N[1], N[2], N[3]);
        s_idx[i] = j - 3;
        s_act[i] = xv / (1.0f + __expf(-xv));
    }
    __syncthreads();

    // Phase 2: one thread per output column (this o-half)
    const int o = oh * 128 + tid;
    const float* __restrict__ cr  = coef + (size_t)o * INDIM * N_COEF;
    const float* __restrict__ rwr = rw   + o * INDIM;
    const float* __restrict__ uwr = uw   + o * INDIM;

    float acc = 0.0f;
    #pragma unroll 4
    for (int i = 0; i < INDIM; ++i) {
        const float* c = cr + i * N_COEF + s_idx[i];
        float4 w = s_w[i];
        float sp = w.x * c[0] + w.y * c[1] + w.z * c[2] + w.w * c[3];
        acc += rwr[i] * s_act[i] + uwr[i] * sp;
    }
    out[b * OUTDIM + o] = acc;
}

extern "C" void kernel_launch(void* const* d_in, const int* in_sizes, int n_in,
                              void* d_out, int out_size)
{
    const float* x    = (const float*)d_in[0];
    const float* grid = (const float*)d_in[1];
    const float* coef = (const float*)d_in[2];
    const float* rw   = (const float*)d_in[3];
    const float* uw   = (const float*)d_in[4];
    float* out = (float*)d_out;

    dim3 g(B_DIM, OUTDIM / 128);
    kan_kernel<<<g, 128>>>(x, grid, coef, rw, uw, out);
}

// round 2
// speedup vs baseline: 7.1294x; 7.1294x over previous
#include <cuda_runtime.h>

#define INDIM   256
#define OUTDIM  256
#define BATCH   128
#define NK      12            // dense slots per input: 11 coef + 1 residual
#define KDIM    (INDIM * NK)  // 3072
#define KS      16            // split-K factor
#define KCH     (KDIM / KS)   // 192
#define TB      8             // batch rows per GEMM block

// Scratch (allocation-free per harness rules): 1.5MB + 3MB + 2MB
__device__ float g_W[BATCH * KDIM];
__device__ float g_V[KDIM * OUTDIM];
__device__ float g_part[KS * BATCH * OUTDIM];

// ---------------- Kernel A: per-(b,i) B-spline basis + silu -> dense W row ----
__global__ __launch_bounds__(256)
void kan_basis(const float* __restrict__ x, const float* __restrict__ grid)
{
    const int b = blockIdx.x;
    const int i = threadIdx.x;

    __shared__ float s_g[15];
    if (i < 15) s_g[i] = grid[i];   // grid is broadcast; first 15 floats are the knots
    __syncthreads();

    const float xv = x[b * INDIM + i];

    int j = 0;
    #pragma unroll
    for (int t = 1; t <= 13; ++t) j += (xv >= s_g[t]) ? 1 : 0;
    j = max(min(j, 10), 3);

    float lft[4], rgt[4];
    #pragma unroll
    for (int t = 1; t <= 3; ++t) { lft[t] = xv - s_g[j + 1 - t]; rgt[t] = s_g[j + t] - xv; }

    float N[4];
    N[0] = 1.0f;
    #pragma unroll
    for (int p = 1; p <= 3; ++p) {
        float saved = 0.0f;
        #pragma unroll
        for (int r = 0; r < p; ++r) {
            float temp = N[r] / (rgt[r + 1] + lft[p - r]);
            N[r] = saved + rgt[r + 1] * temp;
            saved = lft[p - r] * temp;
        }
        N[p] = saved;
    }

    const int idx = j - 3;   // coef window start, 0..7

    float w[NK];
    #pragma unroll
    for (int k = 0; k < 11; ++k) {
        float v = 0.0f;
        #pragma unroll
        for (int r = 0; r < 4; ++r)
            if (k - r == idx) v = N[r];   // fully unrolled -> predicated selects, no local mem
        w[k] = v;
    }
    w[11] = xv / (1.0f + __expf(-xv));    // silu

    float4* dst = (float4*)&g_W[(b * INDIM + i) * NK];   // 48B-aligned
    dst[0] = make_float4(w[0], w[1], w[2],  w[3]);
    dst[1] = make_float4(w[4], w[5], w[6],  w[7]);
    dst[2] = make_float4(w[8], w[9], w[10], w[11]);
}

// ---------------- Kernel B: fold uw/rw into coef, transpose to V[k][o] --------
__global__ __launch_bounds__(256)
void kan_vbuild(const float* __restrict__ coef,
                const float* __restrict__ rw,
                const float* __restrict__ uw)
{
    const int i = blockIdx.x;
    const int o = threadIdx.x;

    const float* c = coef + ((size_t)o * INDIM + i) * 11;
    const float u = uw[o * INDIM + i];
    const float r = rw[o * INDIM + i];

    #pragma unroll
    for (int k = 0; k < 11; ++k)
        g_V[(i * NK + k) * OUTDIM + o] = u * c[k];     // coalesced stores over o
    g_V[(i * NK + 11) * OUTDIM + o] = r;
}

// ---------------- Kernel C: split-K GEMM  part[ks][b][o] = W-tile x V-chunk ---
__global__ __launch_bounds__(256)
void kan_gemm()
{
    __shared__ float s_W[KCH * TB];    // [k][tb], 6KB

    const int b0 = blockIdx.x * TB;
    const int k0 = blockIdx.y * KCH;
    const int o  = threadIdx.x;

    for (int idx = threadIdx.x; idx < TB * KCH; idx += 256) {
        int tb = idx / KCH, k = idx % KCH;
        s_W[k * TB + tb] = g_W[(b0 + tb) * KDIM + k0 + k];   // coalesced global reads
    }
    __syncthreads();

    float acc[TB];
    #pragma unroll
    for (int t = 0; t < TB; ++t) acc[t] = 0.0f;

    const float* Vp = g_V + (size_t)k0 * OUTDIM + o;

    #pragma unroll 4
    for (int k = 0; k < KCH; ++k) {
        float v = Vp[k * OUTDIM];                         // coalesced over o
        const float4* wp = (const float4*)&s_W[k * TB];   // broadcast LDS.128 x2
        float4 a = wp[0], c = wp[1];
        acc[0] += a.x * v; acc[1] += a.y * v; acc[2] += a.z * v; acc[3] += a.w * v;
        acc[4] += c.x * v; acc[5] += c.y * v; acc[6] += c.z * v; acc[7] += c.w * v;
    }

    float* pp = g_part + (size_t)blockIdx.y * (BATCH * OUTDIM) + b0 * OUTDIM + o;
    #pragma unroll
    for (int t = 0; t < TB; ++t) pp[t * OUTDIM] = acc[t];  // coalesced, no atomics
}

// ---------------- Kernel D: reduce split-K partials ---------------------------
__global__ __launch_bounds__(256)
void kan_reduce(float* __restrict__ out)
{
    const int idx = blockIdx.x * 256 + threadIdx.x;
    float s = 0.0f;
    #pragma unroll
    for (int z = 0; z < KS; ++z) s += g_part[z * (BATCH * OUTDIM) + idx];
    out[idx] = s;
}

// ------------------------------------------------------------------------------
extern "C" void kernel_launch(void* const* d_in, const int* in_sizes, int n_in,
                              void* d_out, int out_size)
{
    const float* x    = (const float*)d_in[0];
    const float* grid = (const float*)d_in[1];
    const float* coef = (const float*)d_in[2];
    const float* rw   = (const float*)d_in[3];
    const float* uw   = (const float*)d_in[4];
    float* out = (float*)d_out;

    kan_basis <<<BATCH, 256>>>(x, grid);
    kan_vbuild<<<INDIM, 256>>>(coef, rw, uw);
    kan_gemm  <<<dim3(BATCH / TB, KS), 256>>>();
    kan_reduce<<<(BATCH * OUTDIM) / 256, 256>>>(out);
}

// round 4
// speedup vs baseline: 8.7769x; 1.2311x over previous
#include <cuda_runtime.h>

#define INDIM   256
#define OUTDIM  256
#define BATCH   128
#define NK      12            // dense slots per input: 11 coef + 1 residual
#define KDIM    (INDIM * NK)  // 3072
#define KS      16            // k-splits (16 inputs each)
#define IPC     (INDIM / KS)  // 16 inputs per chunk
#define KCH     (IPC * NK)    // 192 dense k per chunk
#define TB      16            // batch rows per GEMM block
#define OT      128           // output cols per GEMM block

__device__ float g_V[KDIM * OUTDIM];            // 3 MB  folded+transposed weights
__device__ float g_part[KS * BATCH * OUTDIM];   // 2 MB  split-K partials

// ---- Kernel 1: fold uw/rw into coef and transpose -> V[k][o], fully coalesced
__global__ __launch_bounds__(256)
void kan_vbuild(const float* __restrict__ coef,
                const float* __restrict__ rw,
                const float* __restrict__ uw)
{
    __shared__ float s[32 * 105];                // [o_l][i_l*13+k], padded
    const int o0 = blockIdx.x * 32;
    const int i0 = blockIdx.y * 8;
    const int t  = threadIdx.x;

    {   // load side: thread=(o_l,i_l), 11 consecutive floats per thread
        const int o_l = t >> 3, i_l = t & 7;
        const int oi = (o0 + o_l) * INDIM + (i0 + i_l);
        const float u = uw[oi], r = rw[oi];
        const float* c = coef + (size_t)oi * 11;
        float* sp = s + o_l * 105 + i_l * 13;
        #pragma unroll
        for (int k = 0; k < 11; ++k) sp[k] = u * c[k];
        sp[11] = r;
    }
    __syncthreads();
    {   // store side: 32 consecutive o per warp-store -> coalesced
        const int o_l = t & 31;
        const int w   = t >> 5;                  // 0..7
        #pragma unroll
        for (int q = 0; q < 12; ++q) {
            int pair = w + q * 8;                // 0..95 = 8 i x 12 k
            int i_l = pair / NK, k = pair % NK;
            g_V[((size_t)(i0 + i_l) * NK + k) * OUTDIM + o0 + o_l] =
                s[o_l * 105 + i_l * 13 + k];
        }
    }
}

// ---- Kernel 2: split-K GEMM with in-kernel basis build + f32x2 dual FMA -----
__global__ __launch_bounds__(256)
void kan_gemm(const float* __restrict__ x, const float* __restrict__ grid)
{
    __shared__ __align__(16) float s_W[KCH * TB];   // [k_local][b_l], 16B-aligned for LDS.128
    __shared__ float s_g[16];

    const int b0 = blockIdx.x * TB;
    const int o0 = blockIdx.y * OT;
    const int ks = blockIdx.z;
    const int i0 = ks * IPC;
    const int t  = threadIdx.x;

    if (t < 15) s_g[t] = grid[t];
    __syncthreads();

    // ---- basis phase: one (b,i) pair per thread, de Boor -> 12 dense slots
    {
        const int b_l = t & 15, i_l = t >> 4;
        const float xv = x[(b0 + b_l) * INDIM + i0 + i_l];

        int j = 0;
        #pragma unroll
        for (int q = 1; q <= 13; ++q) j += (xv >= s_g[q]) ? 1 : 0;
        j = max(min(j, 10), 3);

        float lft[4], rgt[4];
        #pragma unroll
        for (int q = 1; q <= 3; ++q) { lft[q] = xv - s_g[j + 1 - q]; rgt[q] = s_g[j + q] - xv; }

        float N[4];
        N[0] = 1.0f;
        #pragma unroll
        for (int p = 1; p <= 3; ++p) {
            float saved = 0.0f;
            #pragma unroll
            for (int r = 0; r < p; ++r) {
                float temp = N[r] / (rgt[r + 1] + lft[p - r]);
                N[r] = saved + rgt[r + 1] * temp;
                saved = lft[p - r] * temp;
            }
            N[p] = saved;
        }
        const int idx = j - 3;                   // 0..7

        float w[NK];
        #pragma unroll
        for (int k = 0; k < 11; ++k) {
            float v = 0.0f;
            #pragma unroll
            for (int r = 0; r < 4; ++r)
                if (k - r == idx) v = N[r];
            w[k] = v;
        }
        w[11] = xv / (1.0f + __expf(-xv));       // silu

        #pragma unroll
        for (int k = 0; k < NK; ++k)
            s_W[(i_l * NK + k) * TB + b_l] = w[k];
    }
    __syncthreads();

    // ---- main loop: thread = (o_l, bg); 8 b-rows as 4 packed f32x2 accums
    const int o_l = t & 127;
    const int bg  = t >> 7;                      // 0..1

    unsigned long long acc2[4] = {0ull, 0ull, 0ull, 0ull};   // == {0.f,0.f} x4

    const float* Vp = g_V + (size_t)(i0 * NK) * OUTDIM + o0 + o_l;

    #pragma unroll 8
    for (int k = 0; k < KCH; ++k) {
        float v = Vp[(size_t)k * OUTDIM];                    // coalesced, L2-hot
        unsigned long long v2;
        asm("mov.b64 %0, {%1, %1};" : "=l"(v2) : "r"(__float_as_uint(v)));
        const ulonglong2* wp = (const ulonglong2*)&s_W[k * TB + bg * 8];
        ulonglong2 w01 = wp[0];                              // LDS.128 broadcast
        ulonglong2 w23 = wp[1];
        asm("fma.rn.f32x2 %0, %1, %2, %0;" : "+l"(acc2[0]) : "l"(w01.x), "l"(v2));
        asm("fma.rn.f32x2 %0, %1, %2, %0;" : "+l"(acc2[1]) : "l"(w01.y), "l"(v2));
        asm("fma.rn.f32x2 %0, %1, %2, %0;" : "+l"(acc2[2]) : "l"(w23.x), "l"(v2));
        asm("fma.rn.f32x2 %0, %1, %2, %0;" : "+l"(acc2[3]) : "l"(w23.y), "l"(v2));
    }

    float* pp = g_part + ((size_t)ks * BATCH + b0 + bg * 8) * OUTDIM + o0 + o_l;
    #pragma unroll
    for (int j = 0; j < 4; ++j) {
        unsigned int lo, hi;
        asm("mov.b64 {%0, %1}, %2;" : "=r"(lo), "=r"(hi) : "l"(acc2[j]));
        pp[(2 * j)     * OUTDIM] = __uint_as_float(lo);
        pp[(2 * j + 1) * OUTDIM] = __uint_as_float(hi);
    }
}

// ---- Kernel 3: reduce split-K partials ---------------------------------------
__global__ __launch_bounds__(256)
void kan_reduce(float* __restrict__ out)
{
    const int idx = blockIdx.x * 256 + threadIdx.x;
    float s = 0.0f;
    #pragma unroll
    for (int z = 0; z < KS; ++z) s += g_part[z * (BATCH * OUTDIM) + idx];
    out[idx] = s;
}

// ------------------------------------------------------------------------------
extern "C" void kernel_launch(void* const* d_in, const int* in_sizes, int n_in,
                              void* d_out, int out_size)
{
    const float* x    = (const float*)d_in[0];
    const float* grid = (const float*)d_in[1];
    const float* coef = (const float*)d_in[2];
    const float* rw   = (const float*)d_in[3];
    const float* uw   = (const float*)d_in[4];
    float* out = (float*)d_out;

    kan_vbuild<<<dim3(OUTDIM / 32, INDIM / 8), 256>>>(coef, rw, uw);
    kan_gemm  <<<dim3(BATCH / TB, OUTDIM / OT, KS), 256>>>(x, grid);
    kan_reduce<<<(BATCH * OUTDIM) / 256, 256>>>(out);
}

// round 6
// speedup vs baseline: 10.3105x; 1.1747x over previous
#include <cuda_runtime.h>

#define INDIM   256
#define OUTDIM  256
#define BATCH   128
#define NK      12                  // dense slots per input: 11 coef + 1 residual
#define KS      16                  // k-splits over inputs
#define IPC     (INDIM / KS)        // 16 inputs per chunk
#define KCH     (IPC * NK)          // 192 dense k per chunk
#define OT      32                  // output cols per block
#define VSTR    33                  // padded s_V row stride (conflict-free both ways)

#define SMEM_V  (KCH * VSTR)                    // 6336 floats
#define SMEM_W  (KCH * BATCH)                   // 24576 floats
#define DYN_SMEM ((SMEM_V + SMEM_W) * 4)        // 123648 bytes

__device__ float g_part[KS * BATCH * OUTDIM];   // 2 MB split-K partials

// ---- Kernel 1: fused fold + basis + split-K GEMM ----------------------------
__global__ __launch_bounds__(256)
void kan_gemm(const float* __restrict__ x,
              const float* __restrict__ grid,
              const float* __restrict__ coef,
              const float* __restrict__ rw,
              const float* __restrict__ uw)
{
    extern __shared__ __align__(16) float dyn[];
    float* s_V = dyn;                // [k][o_l] stride VSTR
    float* s_W = dyn + SMEM_V;       // [k][b]   stride 128

    __shared__ float s_g[16];
    __shared__ float s_u[OT * IPC];  // uw tile [o_l*16 + i_l]
    __shared__ float s_r[OT * IPC];  // rw tile

    const int o0 = blockIdx.x * OT;
    const int ks = blockIdx.y;
    const int i0 = ks * IPC;
    const int t  = threadIdx.x;

    if (t < 15) s_g[t] = grid[t];

    // stage uw/rw tiles (16 consecutive i per lane-run -> coalesced 64B chunks)
    #pragma unroll
    for (int q = t; q < OT * IPC; q += 256) {
        const int o_l = q >> 4, i_l = q & 15;
        const int gi = (o0 + o_l) * INDIM + i0 + i_l;
        s_u[q] = uw[gi];
        s_r[q] = rw[gi];
    }
    __syncthreads();

    // fold coef * uw -> s_V (global reads coalesced; smem stores conflict-free)
    #pragma unroll
    for (int idx = t; idx < OT * IPC * 11; idx += 256) {
        const int o_l = idx / 176;           // 176 = 16 i * 11 k
        const int rem = idx - o_l * 176;
        const int i_l = rem / 11;
        const int kk  = rem - i_l * 11;
        const float c = coef[(size_t)(o0 + o_l) * (INDIM * 11) + (i0 + i_l) * 11 + kk];
        s_V[(i_l * NK + kk) * VSTR + o_l] = s_u[o_l * IPC + i_l] * c;
    }
    #pragma unroll
    for (int q = t; q < OT * IPC; q += 256) {
        const int o_l = q >> 4, i_l = q & 15;
        s_V[(i_l * NK + 11) * VSTR + o_l] = s_r[q];
    }

    // basis: thread -> (b = t&127, i_l stepping by 2); smem stores stride-1 in b
    #pragma unroll
    for (int p = t; p < BATCH * IPC; p += 256) {
        const int b   = p & 127;
        const int i_l = p >> 7;
        const float xv = x[b * INDIM + i0 + i_l];

        int j = 0;
        #pragma unroll
        for (int q = 1; q <= 13; ++q) j += (xv >= s_g[q]) ? 1 : 0;
        j = max(min(j, 10), 3);

        float lft[4], rgt[4];
        #pragma unroll
        for (int q = 1; q <= 3; ++q) { lft[q] = xv - s_g[j + 1 - q]; rgt[q] = s_g[j + q] - xv; }

        float N[4];
        N[0] = 1.0f;
        #pragma unroll
        for (int pp = 1; pp <= 3; ++pp) {
            float saved = 0.0f;
            #pragma unroll
            for (int r = 0; r < pp; ++r) {
                float temp = N[r] / (rgt[r + 1] + lft[pp - r]);
                N[r] = saved + rgt[r + 1] * temp;
                saved = lft[pp - r] * temp;
            }
            N[pp] = saved;
        }
        const int widx = j - 3;              // 0..7

        float w[NK];
        #pragma unroll
        for (int k = 0; k < 11; ++k) {
            float v = 0.0f;
            #pragma unroll
            for (int r = 0; r < 4; ++r)
                if (k - r == widx) v = N[r];
            w[k] = v;
        }
        w[11] = xv / (1.0f + __expf(-xv));   // silu

        #pragma unroll
        for (int k = 0; k < NK; ++k)
            s_W[(i_l * NK + k) * BATCH + b] = w[k];
    }
    __syncthreads();

    // main loop: thread = (o_l, bg); 16 b-rows as 8 packed f32x2 accumulators
    const int o_l = t & 31;
    const int bg  = t >> 5;                  // 0..7, constant within a warp
    const int bb  = bg * 16;

    unsigned long long acc2[8];
    #pragma unroll
    for (int j = 0; j < 8; ++j) acc2[j] = 0ull;

    #pragma unroll 4
    for (int k = 0; k < KCH; ++k) {
        const float v = s_V[k * VSTR + o_l];         // conflict-free LDS.32
        unsigned long long v2;
        asm("mov.b64 %0, {%1, %1};" : "=l"(v2) : "r"(__float_as_uint(v)));
        const ulonglong2* wp = (const ulonglong2*)&s_W[k * BATCH + bb];  // 64B-aligned
        ulonglong2 w01 = wp[0];                      // broadcast LDS.128 x4
        ulonglong2 w23 = wp[1];
        ulonglong2 w45 = wp[2];
        ulonglong2 w67 = wp[3];
        asm("fma.rn.f32x2 %0, %1, %2, %0;" : "+l"(acc2[0]) : "l"(w01.x), "l"(v2));
        asm("fma.rn.f32x2 %0, %1, %2, %0;" : "+l"(acc2[1]) : "l"(w01.y), "l"(v2));
        asm("fma.rn.f32x2 %0, %1, %2, %0;" : "+l"(acc2[2]) : "l"(w23.x), "l"(v2));
        asm("fma.rn.f32x2 %0, %1, %2, %0;" : "+l"(acc2[3]) : "l"(w23.y), "l"(v2));
        asm("fma.rn.f32x2 %0, %1, %2, %0;" : "+l"(acc2[4]) : "l"(w45.x), "l"(v2));
        asm("fma.rn.f32x2 %0, %1, %2, %0;" : "+l"(acc2[5]) : "l"(w45.y), "l"(v2));
        asm("fma.rn.f32x2 %0, %1, %2, %0;" : "+l"(acc2[6]) : "l"(w67.x), "l"(v2));
        asm("fma.rn.f32x2 %0, %1, %2, %0;" : "+l"(acc2[7]) : "l"(w67.y), "l"(v2));
    }

    float* pp = g_part + ((size_t)ks * BATCH + bb) * OUTDIM + o0 + o_l;
    #pragma unroll
    for (int j = 0; j < 8; ++j) {
        unsigned int lo, hi;
        asm("mov.b64 {%0, %1}, %2;" : "=r"(lo), "=r"(hi) : "l"(acc2[j]));
        pp[(2 * j)     * OUTDIM] = __uint_as_float(lo);   // coalesced over o_l
        pp[(2 * j + 1) * OUTDIM] = __uint_as_float(hi);
    }
}

// ---- Kernel 2: reduce split-K partials (float4, MLP=16) ---------------------
__global__ __launch_bounds__(256)
void kan_reduce(float4* __restrict__ out)
{
    const int idx = blockIdx.x * 256 + threadIdx.x;   // 8192 float4
    const float4* p = (const float4*)g_part;
    float4 s = make_float4(0.f, 0.f, 0.f, 0.f);
    #pragma unroll
    for (int z = 0; z < KS; ++z) {
        float4 v = p[(size_t)z * (BATCH * OUTDIM / 4) + idx];
        s.x += v.x; s.y += v.y; s.z += v.z; s.w += v.w;
    }
    out[idx] = s;
}

// ------------------------------------------------------------------------------
extern "C" void kernel_launch(void* const* d_in, const int* in_sizes, int n_in,
                              void* d_out, int out_size)
{
    const float* x    = (const float*)d_in[0];
    const float* grid = (const float*)d_in[1];
    const float* coef = (const float*)d_in[2];
    const float* rw   = (const float*)d_in[3];
    const float* uw   = (const float*)d_in[4];

    cudaFuncSetAttribute(kan_gemm, cudaFuncAttributeMaxDynamicSharedMemorySize, DYN_SMEM);

    kan_gemm  <<<dim3(OUTDIM / OT, KS), 256, DYN_SMEM>>>(x, grid, coef, rw, uw);
    kan_reduce<<<(BATCH * OUTDIM / 4) / 256, 256>>>((float4*)d_out);
}